// round 6
// baseline (speedup 1.0000x reference)
#include <cuda_runtime.h>

// Potts energy: out[b] = sum_{i<=j} W[i,j] * [(1-x_i)(1-x_j) + x_i*x_j]
// Expand: (1-x_i)(1-x_j)+x_i x_j = 1 - x_i - x_j + 2 x_i x_j
// Per 64x64 tile U = masked W:
//   E_tile(b) = Wsum - sum_i rs_i x_bi - sum_j cs_j x_bj + 2 sum_ij U_ij x_bi x_bj
// Quadratic part packed over batch pairs with W duplicated as (w,w) u64.

#define Bb      128
#define Nn      1024
#define T       64
#define NT      16
#define NTILES  136
#define WDS     66      // Wdup row stride (u64)
#define XS      66      // Vi2/Vj2 row stride (u64)
#define THREADS 512

__device__ float        g_accum[Bb];
__device__ unsigned int g_count;

__device__ __forceinline__ unsigned long long pack2(float lo, float hi) {
    unsigned long long r;
    asm("mov.b64 %0, {%1, %2};" : "=l"(r) : "f"(lo), "f"(hi));
    return r;
}
__device__ __forceinline__ void unpack2(unsigned long long v, float& lo, float& hi) {
    asm("mov.b64 {%0, %1}, %2;" : "=f"(lo), "=f"(hi) : "l"(v));
}
__device__ __forceinline__ unsigned long long fma2(unsigned long long a,
                                                   unsigned long long b,
                                                   unsigned long long c) {
    unsigned long long d;
    asm("fma.rn.f32x2 %0, %1, %2, %3;" : "=l"(d) : "l"(a), "l"(b), "l"(c));
    return d;
}

extern __shared__ unsigned long long sm[];

__global__ void __launch_bounds__(THREADS, 1)
potts_k(const float* __restrict__ V,   // [128,1024]
        const float* __restrict__ W,   // [1024,1024]
        float* __restrict__ out)       // [128]
{
    unsigned long long* Wd = sm;              // [64][WDS] u64 (w,w) dup, masked
    unsigned long long* Xi = sm + 64 * WDS;   // [64 i][XS] u64 x-pairs over b
    unsigned long long* Xj = Xi + 64 * XS;    // [64 j][XS]
    float* fb   = (float*)(Xj + 64 * XS);
    float* cs   = fb;                         // [64]
    float* rs   = fb + 64;                    // [64]
    float* wsum = fb + 128;                   // [1]
    float* redq = fb + 132;                   // [16][32]
    float* redr = fb + 132 + 512;             // [16][128]
    float* rsp  = redq;                       // alias scratch [64][8]
    float* csp  = redr;                       // alias scratch [64][8]

    const int tid  = threadIdx.x;
    const int warp = tid >> 5;
    const int lane = tid & 31;
    const int bq   = warp & 3;                // b-quarter (32 b)
    const int jq   = warp >> 2;               // j-quarter (16 j)
    const int bgl  = lane >> 2;               // 0..7  -> 4 b each
    const int jgl  = lane & 3;                // 0..3  -> 4 j each
    const int bgidx = bq * 8 + bgl;           // b-pair-pair index (0..31)
    const int jbase = jq * 16 + jgl * 4;      // first of this thread's 4 j

    // ---- tile (bi,bj) from linear upper-tri index ----
    int k = blockIdx.x;
    int bi = 0;
    while (k >= NT - bi) { k -= NT - bi; bi++; }
    const int bj  = bi + k;
    const int gi0 = bi * T;
    const int gj0 = bj * T;
    const bool diag = (bi == bj);

    // ---- stage W tile as duplicated u64, masked (no transpose) ----
    #pragma unroll
    for (int it = 0; it < 2; it++) {
        int idx = it * THREADS + tid;      // 1024 float4
        int ii  = idx >> 4;
        int q   = idx & 15;
        float4 w = *(const float4*)(W + (size_t)(gi0 + ii) * Nn + gj0 + q * 4);
        int j0 = q * 4;
        if (diag) {
            if (ii > j0 + 0) w.x = 0.0f;
            if (ii > j0 + 1) w.y = 0.0f;
            if (ii > j0 + 2) w.z = 0.0f;
            if (ii > j0 + 3) w.w = 0.0f;
        }
        ulonglong2* dst = (ulonglong2*)(Wd + ii * WDS + j0);
        dst[0] = make_ulonglong2(pack2(w.x, w.x), pack2(w.y, w.y));
        dst[1] = make_ulonglong2(pack2(w.z, w.z), pack2(w.w, w.w));
    }

    // ---- stage V slices as x-pairs over b:  X[i][b>>1] halves ----
    #pragma unroll
    for (int it = 0; it < 4; it++) {
        int idx = it * THREADS + tid;      // 2048 float4
        int b   = idx >> 4;
        int q   = idx & 15;
        float4 a = *(const float4*)(V + (size_t)b * Nn + gi0 + q * 4);
        float4 c = *(const float4*)(V + (size_t)b * Nn + gj0 + q * 4);
        float* xi = (float*)Xi;
        float* xj = (float*)Xj;
        int half = b & 1, bp = b >> 1;
        xi[((q * 4 + 0) * XS + bp) * 2 + half] = a.x;
        xi[((q * 4 + 1) * XS + bp) * 2 + half] = a.y;
        xi[((q * 4 + 2) * XS + bp) * 2 + half] = a.z;
        xi[((q * 4 + 3) * XS + bp) * 2 + half] = a.w;
        xj[((q * 4 + 0) * XS + bp) * 2 + half] = c.x;
        xj[((q * 4 + 1) * XS + bp) * 2 + half] = c.y;
        xj[((q * 4 + 2) * XS + bp) * 2 + half] = c.z;
        xj[((q * 4 + 3) * XS + bp) * 2 + half] = c.w;
    }
    __syncthreads();

    // ---- cooperative row/col sums of masked tile (lo halves of Wd) ----
    {
        const float* Wlo = (const float*)Wd;   // lo half at even float index
        int r = tid >> 3, c = tid & 7;
        float pr = 0.0f, pc = 0.0f;
        #pragma unroll
        for (int t = 0; t < 8; t++) {
            pr += Wlo[(r * WDS + c * 8 + t) * 2];    // row r sum over j
            pc += Wlo[((c * 8 + t) * WDS + r) * 2];  // col r sum over i
        }
        rsp[r * 8 + c] = pr;
        csp[r * 8 + c] = pc;
    }
    __syncthreads();
    if (tid < 64) {
        float s = 0.0f;
        #pragma unroll
        for (int c = 0; c < 8; c++) s += rsp[tid * 8 + c];
        rs[tid] = s;
    } else if (tid < 128) {
        int j = tid - 64;
        float s = 0.0f;
        #pragma unroll
        for (int c = 0; c < 8; c++) s += csp[j * 8 + c];
        cs[j] = s;
    }
    __syncthreads();
    if (warp == 0) {
        float v = cs[lane] + cs[lane + 32];
        #pragma unroll
        for (int o = 16; o > 0; o >>= 1) v += __shfl_down_sync(0xffffffffu, v, o);
        if (lane == 0) wsum[0] = v;
    }
    __syncthreads();

    // ---- quadratic main loop: packed s1 over (b0,b1)/(b2,b3) x 4 j ----
    unsigned long long a00 = 0, a01 = 0, a10 = 0, a11 = 0;
    unsigned long long a20 = 0, a21 = 0, a30 = 0, a31 = 0;

    #pragma unroll 16
    for (int i = 0; i < T; i++) {
        ulonglong2 xp = *(const ulonglong2*)(Xi + i * XS + 2 * bgidx);
        ulonglong2 wA = *(const ulonglong2*)(Wd + i * WDS + jbase);
        ulonglong2 wB = *(const ulonglong2*)(Wd + i * WDS + jbase + 2);
        a00 = fma2(wA.x, xp.x, a00);  a01 = fma2(wA.x, xp.y, a01);
        a10 = fma2(wA.y, xp.x, a10);  a11 = fma2(wA.y, xp.y, a11);
        a20 = fma2(wB.x, xp.x, a20);  a21 = fma2(wB.x, xp.y, a21);
        a30 = fma2(wB.y, xp.x, a30);  a31 = fma2(wB.y, xp.y, a31);
    }

    // ---- epilogue: q(b) += x_bj * (2*s1_bj - cs_j), stays packed ----
    const unsigned long long twodup = pack2(2.0f, 2.0f);
    unsigned long long q0 = 0, q1 = 0;
    {
        unsigned long long accs[4][2] = {{a00,a01},{a10,a11},{a20,a21},{a30,a31}};
        #pragma unroll
        for (int jg = 0; jg < 4; jg++) {
            int j = jbase + jg;
            float csj = cs[j];
            unsigned long long ncs = pack2(-csj, -csj);
            unsigned long long t0 = fma2(accs[jg][0], twodup, ncs);
            unsigned long long t1 = fma2(accs[jg][1], twodup, ncs);
            ulonglong2 vj = *(const ulonglong2*)(Xj + j * XS + 2 * bgidx);
            q0 = fma2(vj.x, t0, q0);
            q1 = fma2(vj.y, t1, q1);
        }
    }
    {
        float f0, f1, f2, f3;
        unpack2(q0, f0, f1);
        unpack2(q1, f2, f3);
        // FIX (R5 bug): 4 jgl-lanes share the same (warp,bgl) slot in redq.
        // jgl lives in lane bits [1:0] -> xor-1/xor-2 butterflies sum over jgl.
        #pragma unroll
        for (int o = 1; o <= 2; o <<= 1) {
            f0 += __shfl_xor_sync(0xffffffffu, f0, o);
            f1 += __shfl_xor_sync(0xffffffffu, f1, o);
            f2 += __shfl_xor_sync(0xffffffffu, f2, o);
            f3 += __shfl_xor_sync(0xffffffffu, f3, o);
        }
        if (jgl == 0) {
            float* row = redq + warp * 32 + bgl * 4;
            row[0] = f0; row[1] = f1; row[2] = f2; row[3] = f3;
        }
    }

    // ---- linear rs term: warp w covers i = 4w..4w+3, lane covers 4 b ----
    {
        unsigned long long r0 = 0, r1 = 0;
        int i0 = warp * 4;
        #pragma unroll
        for (int t = 0; t < 4; t++) {
            int i = i0 + t;
            unsigned long long rd = pack2(rs[i], rs[i]);
            ulonglong2 xp = *(const ulonglong2*)(Xi + i * XS + 2 * lane);
            r0 = fma2(rd, xp.x, r0);
            r1 = fma2(rd, xp.y, r1);
        }
        float f0, f1, f2, f3;
        unpack2(r0, f0, f1);
        unpack2(r1, f2, f3);
        float* row = redr + warp * 128 + lane * 4;
        row[0] = f0; row[1] = f1; row[2] = f2; row[3] = f3;
    }
    __syncthreads();

    // ---- final per-b reduction + global accumulate ----
    if (tid < Bb) {
        int tbq = tid >> 5, bl = tid & 31;
        float sq = redq[(0 * 4 + tbq) * 32 + bl] + redq[(1 * 4 + tbq) * 32 + bl]
                 + redq[(2 * 4 + tbq) * 32 + bl] + redq[(3 * 4 + tbq) * 32 + bl];
        float sr = 0.0f;
        #pragma unroll
        for (int w = 0; w < 16; w++) sr += redr[w * 128 + tid];
        atomicAdd(&g_accum[tid], sq - sr + wsum[0]);
    }
    __threadfence();
    __syncthreads();

    __shared__ bool last;
    if (tid == 0) last = (atomicAdd(&g_count, 1u) == NTILES - 1);
    __syncthreads();

    if (last) {
        __threadfence();
        if (tid < Bb) out[tid] = atomicExch(&g_accum[tid], 0.0f);
        if (tid == 0) atomicExch(&g_count, 0u);
    }
}

extern "C" void kernel_launch(void* const* d_in, const int* in_sizes, int n_in,
                              void* d_out, int out_size)
{
    const float* V = (const float*)d_in[0];
    const float* W = (const float*)d_in[1];
    float* out = (float*)d_out;

    const int smem_bytes = (64 * WDS + 2 * 64 * XS) * 8
                         + (132 + 512 + 2048) * 4;   // 112144
    cudaFuncSetAttribute(potts_k, cudaFuncAttributeMaxDynamicSharedMemorySize,
                         smem_bytes);

    potts_k<<<NTILES, THREADS, smem_bytes>>>(V, W, out);
}